// round 10
// baseline (speedup 1.0000x reference)
#include <cuda_runtime.h>

// Problem constants
static constexpr int N_MC = 32;
static constexpr int M    = 8192;
static constexpr int D    = 16;

#define TWOPI_F   6.2831853071795864769f   // rounds to float32(2*pi)
#define NEG_HALF_LOG_2PI -0.9189385332046727f
#define C_EX2     (-0.72134752044448170368f)  // -0.5 * log2(e)
#define LN2_F     0.69314718055994530942f
#define LOG2E_F   1.4426950408889634074f

typedef unsigned long long u64;

// Packed f32x2 broadcast constants (same f32 bits in both lanes)
#define MG2     0x4B4000004B400000ull   // ( 1.5*2^23,  1.5*2^23)
#define NMG2    0xCB400000CB400000ull   // (-1.5*2^23, -1.5*2^23)
#define INV2PI2 0x3E22F9833E22F983ull   // (1/2pi, 1/2pi)
#define NTWOPI2 0xC0C90FDBC0C90FDBull   // (-2pi, -2pi)
#define ONE2    0x3F8000003F800000ull   // (1, 1)

__device__ __forceinline__ float ex2f(float x) {
    float y; asm("ex2.approx.f32 %0, %1;" : "=f"(y) : "f"(x)); return y;
}
__device__ __forceinline__ float lg2f(float x) {
    float y; asm("lg2.approx.f32 %0, %1;" : "=f"(y) : "f"(x)); return y;
}
__device__ __forceinline__ u64 pk(float lo, float hi) {
    u64 r; asm("mov.b64 %0, {%1, %2};" : "=l"(r) : "f"(lo), "f"(hi)); return r;
}
__device__ __forceinline__ void upk(float& lo, float& hi, u64 v) {
    asm("mov.b64 {%0, %1}, %2;" : "=f"(lo), "=f"(hi) : "l"(v));
}
__device__ __forceinline__ u64 fma2(u64 a, u64 b, u64 c) {
    u64 d; asm("fma.rn.f32x2 %0, %1, %2, %3;" : "=l"(d) : "l"(a), "l"(b), "l"(c)); return d;
}
__device__ __forceinline__ u64 add2(u64 a, u64 b) {
    u64 d; asm("add.rn.f32x2 %0, %1, %2;" : "=l"(d) : "l"(a), "l"(b)); return d;
}
__device__ __forceinline__ u64 mul2(u64 a, u64 b) {
    u64 d; asm("mul.rn.f32x2 %0, %1, %2;" : "=l"(d) : "l"(a), "l"(b)); return d;
}

struct Consts {
    u64 s01, s23, m01, m23, i01, i23, b01, b23, w01, w23;
};

// One dim-PAIR, fully packed f32x2 (validated R5-R7: g bit-safe, lq 2-term).
__device__ __forceinline__ void dimpair(
    u64 e2, u64 s2, u64 mu2, u64 i2, u64 b2, u64 w2,
    float& g_lo, float& g_hi, u64& uacc2, u64& P2)
{
    u64 x2 = mul2(e2, s2);
    // ---- g = mod(x+mu, 2pi): magic-rint + exact fma remainder ----
    u64 v2 = add2(x2, mu2);
    u64 q2 = add2(fma2(v2, INV2PI2, MG2), NMG2);
    u64 t2 = fma2(q2, NTWOPI2, v2);
    float tl, th; upk(tl, th, t2);
    if (tl < 0.0f) tl += TWOPI_F;
    if (th < 0.0f) th += TWOPI_F;
    g_lo = tl; g_hi = th;
    // ---- lq: center x, 2-term lattice  p = 1 + w*exp(a|u|) ----
    u64 k2  = add2(fma2(x2, INV2PI2, MG2), NMG2);
    u64 r2  = fma2(k2, NTWOPI2, x2);
    uacc2 = fma2(mul2(r2, r2), i2, uacc2);
    float cl, ch; upk(cl, ch, mul2(r2, b2));
    P2 = mul2(P2, fma2(w2, pk(ex2f(fabsf(cl)), ex2f(fabsf(ch))), ONE2));
}

__device__ __forceinline__ float elem(const float4 e, const Consts& C,
                                      float4* __restrict__ gptr)
{
    float4 g;
    u64 u2 = 0, P2 = ONE2;
    dimpair(pk(e.x, e.y), C.s01, C.m01, C.i01, C.b01, C.w01, g.x, g.y, u2, P2);
    dimpair(pk(e.z, e.w), C.s23, C.m23, C.i23, C.b23, C.w23, g.z, g.w, u2, P2);
    *gptr = g;
    float u0, u1, p0, p1;
    upk(u0, u1, u2); upk(p0, p1, P2);
    return fmaf(u0 + u1, -0.5f, LN2_F * lg2f(p0 * p1));
}

// Single fused kernel: 2^18 threads (1024 blocks — 6.9 blocks/SM, small tail).
// Thread (q, c) with c = m*4 + dq owns dims [4dq, 4dq+4) of MC samples
// n in [4q, 4q+4).  Per-(m,d) constants computed IN REGISTERS (precise
// softplus preserves the bit-exact g path); C_m via shfl over the dq quad.
__global__ void __launch_bounds__(256) relie_fused(
    const float4* __restrict__ eps4,    // 2^20 float4  (n, m, d)
    const float4* __restrict__ gam4,    // M*4 float4
    const float4* __restrict__ mu4,     // M*4 float4
    float4*       __restrict__ g4,      // 2^20 float4
    float*        __restrict__ lq)      // N*M floats
{
    int tid = blockIdx.x * blockDim.x + threadIdx.x;  // 0 .. 2^18-1
    int q   = tid >> 15;                 // n-group: n0 = 4q, q in 0..7
    int c   = tid & 0x7FFF;              // m*4 + dq
    int m   = c >> 2;
    int dq  = c & 3;
    int n0  = q << 2;

    // ---- per-(m,d) constants, 4 dims, in registers ----
    float4 gam = gam4[c];
    float4 mu  = mu4[c];
    float gv[4] = { gam.x, gam.y, gam.z, gam.w };
    float sv[4], iv[4], wv[4], bv[4];
    float ln = 0.0f;
    #pragma unroll
    for (int j = 0; j < 4; j++) {
        float raw = gv[j];
        // EXACT jax.nn.softplus: max(x,0) + log1p(exp(-|x|)), precise libdevice
        float s   = fmaxf(raw, 0.0f) + log1pf(expf(-fabsf(raw)));
        float inv = 1.0f / s;
        float a   = TWOPI_F * inv;
        sv[j] = s;
        iv[j] = inv * inv;
        wv[j] = ex2f(a * a * C_EX2);     // exp(-a^2/2)
        bv[j] = a * inv * LOG2E_F;       // c = r*b = (a*u)*log2(e)
        ln += NEG_HALF_LOG_2PI - LN2_F * lg2f(s);
    }
    // C_m = sum over all 16 dims: reduce over the dq quad (lane&3 == dq)
    ln += __shfl_xor_sync(0xffffffffu, ln, 1);
    ln += __shfl_xor_sync(0xffffffffu, ln, 2);
    float Cm = ln;

    Consts C;
    C.s01 = pk(sv[0], sv[1]); C.s23 = pk(sv[2], sv[3]);
    C.m01 = pk(mu.x,  mu.y);  C.m23 = pk(mu.z,  mu.w);
    C.i01 = pk(iv[0], iv[1]); C.i23 = pk(iv[2], iv[3]);
    C.b01 = pk(bv[0], bv[1]); C.b23 = pk(bv[2], bv[3]);
    C.w01 = pk(wv[0], wv[1]); C.w23 = pk(wv[2], wv[3]);

    // ---- 4 elements: front-batched independent loads (MLP = 4) ----
    const int ROW = M * 4;               // float4 stride per MC sample
    int base = n0 * ROW + c;
    float4 e0 = eps4[base          ];
    float4 e1 = eps4[base +     ROW];
    float4 e2 = eps4[base + 2 * ROW];
    float4 e3 = eps4[base + 3 * ROW];

    float v0 = elem(e0, C, g4 + base          );
    float v1 = elem(e1, C, g4 + base +     ROW);
    float v2 = elem(e2, C, g4 + base + 2 * ROW);
    float v3 = elem(e3, C, g4 + base + 3 * ROW);

    // ---- lq reductions over the dq quad, one per MC sample ----
    v0 += __shfl_xor_sync(0xffffffffu, v0, 1);
    v0 += __shfl_xor_sync(0xffffffffu, v0, 2);
    v1 += __shfl_xor_sync(0xffffffffu, v1, 1);
    v1 += __shfl_xor_sync(0xffffffffu, v1, 2);
    v2 += __shfl_xor_sync(0xffffffffu, v2, 1);
    v2 += __shfl_xor_sync(0xffffffffu, v2, 2);
    v3 += __shfl_xor_sync(0xffffffffu, v3, 1);
    v3 += __shfl_xor_sync(0xffffffffu, v3, 2);
    if (dq == 0) {
        int nm = n0 * M + m;
        lq[nm        ] = v0 + Cm;
        lq[nm +     M] = v1 + Cm;
        lq[nm + 2 * M] = v2 + Cm;
        lq[nm + 3 * M] = v3 + Cm;
    }
}

extern "C" void kernel_launch(void* const* d_in, const int* in_sizes, int n_in,
                              void* d_out, int out_size) {
    const float* eps       = (const float*)d_in[0];  // (32, 8192, 16)
    const float* gamma_raw = (const float*)d_in[1];  // (8192, 16)
    const float* mu        = (const float*)d_in[2];  // (8192, 16)

    float* g_out  = (float*)d_out;                          // N*M*D floats
    float* lq_out = (float*)d_out + (size_t)N_MC * M * D;   // N*M floats

    relie_fused<<<(1 << 18) / 256, 256>>>(
        (const float4*)eps, (const float4*)gamma_raw, (const float4*)mu,
        (float4*)g_out, lq_out);
}

// round 13
// speedup vs baseline: 1.0209x; 1.0209x over previous
#include <cuda_runtime.h>

// Problem constants
static constexpr int N_MC = 32;
static constexpr int M    = 8192;
static constexpr int D    = 16;

#define TWOPI_F   6.2831853071795864769f   // rounds to float32(2*pi)
#define NEG_HALF_LOG_2PI -0.9189385332046727f
#define LN2_F     0.69314718055994530942f
#define K_B       9.0647202836543873894f      // 2*pi * log2(e):   b = K_B  * i2
#define K_W      (-28.476200801864298f)       // -4*pi^2*log2(e)/2: warg = K_W * i2

typedef unsigned long long u64;

// Packed f32x2 broadcast constants (same f32 bits in both lanes)
#define MG2     0x4B4000004B400000ull   // ( 1.5*2^23,  1.5*2^23)
#define NMG2    0xCB400000CB400000ull   // (-1.5*2^23, -1.5*2^23)
#define INV2PI2 0x3E22F9833E22F983ull   // (1/2pi, 1/2pi)
#define NTWOPI2 0xC0C90FDBC0C90FDBull   // (-2pi, -2pi)
#define ONE2    0x3F8000003F800000ull   // (1, 1)

__device__ __forceinline__ float ex2f(float x) {
    float y; asm("ex2.approx.f32 %0, %1;" : "=f"(y) : "f"(x)); return y;
}
__device__ __forceinline__ float lg2f(float x) {
    float y; asm("lg2.approx.f32 %0, %1;" : "=f"(y) : "f"(x)); return y;
}
__device__ __forceinline__ float rcpf(float x) {
    float y; asm("rcp.approx.f32 %0, %1;" : "=f"(y) : "f"(x)); return y;
}
__device__ __forceinline__ u64 pk(float lo, float hi) {
    u64 r; asm("mov.b64 %0, {%1, %2};" : "=l"(r) : "f"(lo), "f"(hi)); return r;
}
__device__ __forceinline__ void upk(float& lo, float& hi, u64 v) {
    asm("mov.b64 {%0, %1}, %2;" : "=f"(lo), "=f"(hi) : "l"(v));
}
__device__ __forceinline__ u64 fma2(u64 a, u64 b, u64 c) {
    u64 d; asm("fma.rn.f32x2 %0, %1, %2, %3;" : "=l"(d) : "l"(a), "l"(b), "l"(c)); return d;
}
__device__ __forceinline__ u64 add2(u64 a, u64 b) {
    u64 d; asm("add.rn.f32x2 %0, %1, %2;" : "=l"(d) : "l"(a), "l"(b)); return d;
}
__device__ __forceinline__ u64 mul2(u64 a, u64 b) {
    u64 d; asm("mul.rn.f32x2 %0, %1, %2;" : "=l"(d) : "l"(a), "l"(b)); return d;
}

struct Consts {
    u64 s01, s23, m01, m23, i01, i23, b01, b23, w01, w23;
};

// One dim-PAIR, fully packed f32x2 (validated R5-R10: g bit-safe, lq 2-term).
__device__ __forceinline__ void dimpair(
    u64 e2, u64 s2, u64 mu2, u64 i2, u64 b2, u64 w2,
    float& g_lo, float& g_hi, u64& uacc2, u64& P2)
{
    u64 x2 = mul2(e2, s2);
    // ---- g = mod(x+mu, 2pi): magic-rint + exact fma remainder ----
    u64 v2 = add2(x2, mu2);
    u64 q2 = add2(fma2(v2, INV2PI2, MG2), NMG2);
    u64 t2 = fma2(q2, NTWOPI2, v2);
    float tl, th; upk(tl, th, t2);
    if (tl < 0.0f) tl += TWOPI_F;
    if (th < 0.0f) th += TWOPI_F;
    g_lo = tl; g_hi = th;
    // ---- lq: center x, 2-term lattice  p = 1 + w*exp(a|u|) ----
    u64 k2  = add2(fma2(x2, INV2PI2, MG2), NMG2);
    u64 r2  = fma2(k2, NTWOPI2, x2);
    uacc2 = fma2(mul2(r2, r2), i2, uacc2);
    float cl, ch; upk(cl, ch, mul2(r2, b2));
    P2 = mul2(P2, fma2(w2, pk(ex2f(fabsf(cl)), ex2f(fabsf(ch))), ONE2));
}

__device__ __forceinline__ float elem(const float4 e, const Consts& C,
                                      float4* __restrict__ gptr)
{
    float4 g;
    u64 u2 = 0, P2 = ONE2;
    dimpair(pk(e.x, e.y), C.s01, C.m01, C.i01, C.b01, C.w01, g.x, g.y, u2, P2);
    dimpair(pk(e.z, e.w), C.s23, C.m23, C.i23, C.b23, C.w23, g.z, g.w, u2, P2);
    *gptr = g;
    float u0, u1, p0, p1;
    upk(u0, u1, u2); upk(p0, p1, P2);
    return fmaf(u0 + u1, -0.5f, LN2_F * lg2f(p0 * p1));
}

// Single fused kernel: 2^18 threads (1024 blocks).  Thread (q, c) with
// c = m*4 + dq owns dims [4dq, 4dq+4) of MC samples n in [4q, 4q+4).
// Preamble trimmed: precise softplus kept (bit-exact g path), but 1/s via
// MUFU rcp.approx, b & w as single FMULs of i2, one lg2 over prod(s).
__global__ void __launch_bounds__(256) relie_fused(
    const float4* __restrict__ eps4,    // 2^20 float4  (n, m, d)
    const float4* __restrict__ gam4,    // M*4 float4
    const float4* __restrict__ mu4,     // M*4 float4
    float4*       __restrict__ g4,      // 2^20 float4
    float*        __restrict__ lq)      // N*M floats
{
    int tid = blockIdx.x * blockDim.x + threadIdx.x;  // 0 .. 2^18-1
    int q   = tid >> 15;                 // n-group: n0 = 4q, q in 0..7
    int c   = tid & 0x7FFF;              // m*4 + dq
    int m   = c >> 2;
    int dq  = c & 3;
    int n0  = q << 2;

    // ---- issue ALL global loads first so DRAM wait overlaps the preamble ----
    const int ROW = M * 4;               // float4 stride per MC sample
    int base = n0 * ROW + c;
    float4 e0  = eps4[base          ];
    float4 e1  = eps4[base +     ROW];
    float4 e2  = eps4[base + 2 * ROW];
    float4 e3  = eps4[base + 3 * ROW];
    float4 gam = gam4[c];
    float4 mu  = mu4[c];

    // ---- per-(m,d) constants, 4 dims, in registers ----
    float gv[4] = { gam.x, gam.y, gam.z, gam.w };
    float sv[4], iv[4], wv[4], bv[4];
    #pragma unroll
    for (int j = 0; j < 4; j++) {
        float raw = gv[j];
        // EXACT jax.nn.softplus: max(x,0) + log1p(exp(-|x|)), precise libdevice
        float s  = fmaxf(raw, 0.0f) + log1pf(expf(-fabsf(raw)));
        float in = rcpf(s);              // approx ok: feeds lq only
        float i2 = in * in;
        sv[j] = s;
        iv[j] = i2;
        wv[j] = ex2f(K_W * i2);          // exp(-a^2/2),  a = 2pi/s
        bv[j] = K_B * i2;                // (a/s)*log2e
    }
    // Cm partial: 4*(-0.5 log 2pi) - ln(prod s) with ONE lg2
    float ln = fmaf(-LN2_F, lg2f(((sv[0] * sv[1]) * sv[2]) * sv[3]),
                    4.0f * NEG_HALF_LOG_2PI);
    // C_m = sum over all 16 dims: reduce over the dq quad (lane&3 == dq)
    ln += __shfl_xor_sync(0xffffffffu, ln, 1);
    ln += __shfl_xor_sync(0xffffffffu, ln, 2);
    float Cm = ln;

    Consts C;
    C.s01 = pk(sv[0], sv[1]); C.s23 = pk(sv[2], sv[3]);
    C.m01 = pk(mu.x,  mu.y);  C.m23 = pk(mu.z,  mu.w);
    C.i01 = pk(iv[0], iv[1]); C.i23 = pk(iv[2], iv[3]);
    C.b01 = pk(bv[0], bv[1]); C.b23 = pk(bv[2], bv[3]);
    C.w01 = pk(wv[0], wv[1]); C.w23 = pk(wv[2], wv[3]);

    float v0 = elem(e0, C, g4 + base          );
    float v1 = elem(e1, C, g4 + base +     ROW);
    float v2 = elem(e2, C, g4 + base + 2 * ROW);
    float v3 = elem(e3, C, g4 + base + 3 * ROW);

    // ---- lq reductions over the dq quad, one per MC sample ----
    v0 += __shfl_xor_sync(0xffffffffu, v0, 1);
    v0 += __shfl_xor_sync(0xffffffffu, v0, 2);
    v1 += __shfl_xor_sync(0xffffffffu, v1, 1);
    v1 += __shfl_xor_sync(0xffffffffu, v1, 2);
    v2 += __shfl_xor_sync(0xffffffffu, v2, 1);
    v2 += __shfl_xor_sync(0xffffffffu, v2, 2);
    v3 += __shfl_xor_sync(0xffffffffu, v3, 1);
    v3 += __shfl_xor_sync(0xffffffffu, v3, 2);
    if (dq == 0) {
        int nm = n0 * M + m;
        lq[nm        ] = v0 + Cm;
        lq[nm +     M] = v1 + Cm;
        lq[nm + 2 * M] = v2 + Cm;
        lq[nm + 3 * M] = v3 + Cm;
    }
}

extern "C" void kernel_launch(void* const* d_in, const int* in_sizes, int n_in,
                              void* d_out, int out_size) {
    const float* eps       = (const float*)d_in[0];  // (32, 8192, 16)
    const float* gamma_raw = (const float*)d_in[1];  // (8192, 16)
    const float* mu        = (const float*)d_in[2];  // (8192, 16)

    float* g_out  = (float*)d_out;                          // N*M*D floats
    float* lq_out = (float*)d_out + (size_t)N_MC * M * D;   // N*M floats

    relie_fused<<<(1 << 18) / 256, 256>>>(
        (const float4*)eps, (const float4*)gamma_raw, (const float4*)mu,
        (float4*)g_out, lq_out);
}